// round 3
// baseline (speedup 1.0000x reference)
#include <cuda_runtime.h>
#include <cstdint>
#include <cstddef>

#define DD 4096
#define MM 8192

// Scratch: Hadamard-rotated, tf32-rounded W [N,K]; tf32-rounded x [M,K].
__device__ __align__(256) float g_Wr[(size_t)DD * DD];
__device__ __align__(256) float g_Xr[(size_t)MM * DD];

// ---------------------------------------------------------------------------
// Kernel 1: row-wise WHT of W, scale 1/64, round to tf32 (RNA).
// ---------------------------------------------------------------------------
__global__ void wht_rows_kernel(const float* __restrict__ W) {
    __shared__ float h[DD];
    const int row = blockIdx.x;
    const float* src = W + (size_t)row * DD;
    for (int i = threadIdx.x; i < DD; i += blockDim.x) h[i] = src[i];
    __syncthreads();
    for (int len = 1; len < DD; len <<= 1) {
        for (int p = threadIdx.x; p < DD / 2; p += blockDim.x) {
            int i = ((p & ~(len - 1)) << 1) | (p & (len - 1));
            float a = h[i], b = h[i + len];
            h[i] = a + b;
            h[i + len] = a - b;
        }
        __syncthreads();
    }
    float* dst = g_Wr + (size_t)row * DD;
    for (int i = threadIdx.x; i < DD; i += blockDim.x) {
        float v = h[i] * 0.015625f;
        uint32_t t;
        asm("cvt.rna.tf32.f32 %0, %1;" : "=r"(t) : "f"(v));
        dst[i] = __uint_as_float(t);
    }
}

// ---------------------------------------------------------------------------
// Kernel 2: round x to tf32 (RNA) so the mma's truncation is exact.
// ---------------------------------------------------------------------------
__global__ void cvt_x_kernel(const float4* __restrict__ x) {
    const int idx = blockIdx.x * blockDim.x + threadIdx.x;   // one float4 each
    float4 v = x[idx];
    uint32_t a, b, c, d;
    asm("cvt.rna.tf32.f32 %0, %1;" : "=r"(a) : "f"(v.x));
    asm("cvt.rna.tf32.f32 %0, %1;" : "=r"(b) : "f"(v.y));
    asm("cvt.rna.tf32.f32 %0, %1;" : "=r"(c) : "f"(v.z));
    asm("cvt.rna.tf32.f32 %0, %1;" : "=r"(d) : "f"(v.w));
    float4 o;
    o.x = __uint_as_float(a); o.y = __uint_as_float(b);
    o.z = __uint_as_float(c); o.w = __uint_as_float(d);
    ((float4*)g_Xr)[idx] = o;
}

// ---------------------------------------------------------------------------
// Kernel 3: tf32 mma.sync GEMM  out[M,N] = Xr[M,K] @ Wr[N,K]^T + bias
// CTA 128x128, TK=32, 3-stage cp.async, 8 warps (4x2), warp tile 32x64.
// Operand fetch via ldmatrix.m8n8.x4 (b16 view of tf32).
// ---------------------------------------------------------------------------
constexpr int TM = 128;
constexpr int TN = 128;
constexpr int TK = 32;                       // floats per K-tile
constexpr int NKT = DD / TK;                 // 128
constexpr int STAGES = 3;
constexpr int RSTRIDE = 36;                  // padded row stride in floats (144B)
constexpr int TILE_FLOATS = 128 * RSTRIDE;
constexpr int STAGE_FLOATS = 2 * TILE_FLOATS;
constexpr int SMEM_TOTAL = STAGES * STAGE_FLOATS * 4;   // 110592 B

__device__ __forceinline__ uint32_t smem_u32(const void* p) {
    return (uint32_t)__cvta_generic_to_shared(p);
}
__device__ __forceinline__ void cp16(uint32_t dst, const void* src) {
    asm volatile("cp.async.cg.shared.global [%0], [%1], 16;\n" :: "r"(dst), "l"(src));
}
__device__ __forceinline__ void ldsm4(uint32_t* r, uint32_t addr) {
    asm volatile("ldmatrix.sync.aligned.m8n8.x4.shared.b16 {%0,%1,%2,%3}, [%4];"
                 : "=r"(r[0]), "=r"(r[1]), "=r"(r[2]), "=r"(r[3]) : "r"(addr));
}

__device__ __forceinline__ void issue_stage(const float* __restrict__ A,
                                            const float* __restrict__ B,
                                            int m0, int n0, int kt, int slot,
                                            uint32_t sbase, int tid) {
    const uint32_t stA = sbase + (uint32_t)(slot * STAGE_FLOATS * 4);
    const uint32_t stB = stA + TILE_FLOATS * 4;
#pragma unroll
    for (int i = 0; i < 4; ++i) {
        const int idx = tid + i * 256;       // 1024 chunks of 16B
        const int row = idx >> 3;
        const int col = idx & 7;
        cp16(stA + row * (RSTRIDE * 4) + col * 16,
             A + (size_t)(m0 + row) * DD + kt * TK + col * 4);
    }
#pragma unroll
    for (int i = 0; i < 4; ++i) {
        const int idx = tid + i * 256;
        const int row = idx >> 3;
        const int col = idx & 7;
        cp16(stB + row * (RSTRIDE * 4) + col * 16,
             B + (size_t)(n0 + row) * DD + kt * TK + col * 4);
    }
    asm volatile("cp.async.commit_group;\n" ::: "memory");
}

__device__ __forceinline__ void mma_tf32(float* c, const uint32_t* a, const uint32_t* b) {
    asm volatile(
        "mma.sync.aligned.m16n8k8.row.col.f32.tf32.tf32.f32 "
        "{%0,%1,%2,%3}, {%4,%5,%6,%7}, {%8,%9}, {%0,%1,%2,%3};"
        : "+f"(c[0]), "+f"(c[1]), "+f"(c[2]), "+f"(c[3])
        : "r"(a[0]), "r"(a[1]), "r"(a[2]), "r"(a[3]),
          "r"(b[0]), "r"(b[1]));
}

__global__ void __launch_bounds__(256, 1)
gemm_tf32_kernel(const float* __restrict__ bias, float* __restrict__ out) {
    extern __shared__ float smem[];
    const uint32_t sbase = smem_u32(smem);
    const int tid = threadIdx.x;
    const int wid = tid >> 5;
    const int lane = tid & 31;
    const int g = lane >> 2;            // groupID 0..7
    const int nc2 = (lane & 3) * 2;     // accumulator n-column base
    const int wm = wid & 3;             // 4 warps along M
    const int wn = wid >> 2;            // 2 warps along N

    // ldmatrix per-lane row/column offsets (in floats, added to k offset)
    const int a_row = lane & 15;                       // within 16-row tile
    const int a_kofs = (lane >> 4) << 2;               // 0 or 4
    const int b_row = ((lane >> 4) << 3) + (lane & 7); // within 16 N-rows
    const int b_kofs = ((lane >> 3) & 1) << 2;         // 0 or 4

    // CTA swizzle: groups of 16 M-tiles sweep all N-tiles (L2 locality).
    constexpr int PN = DD / TN;         // 32
    constexpr int G = 16;
    const int pid = blockIdx.x;
    const int grp = pid / (G * PN);
    const int pm = grp * G + (pid % G);
    const int pn = (pid % (G * PN)) / G;
    const int m0 = pm * TM;
    const int n0 = pn * TN;

    float acc[2][8][4];
#pragma unroll
    for (int mi = 0; mi < 2; ++mi)
#pragma unroll
        for (int ni = 0; ni < 8; ++ni)
#pragma unroll
            for (int v = 0; v < 4; ++v) acc[mi][ni][v] = 0.0f;

    // prologue
#pragma unroll
    for (int kt = 0; kt < STAGES - 1; ++kt)
        issue_stage(g_Xr, g_Wr, m0, n0, kt, kt, sbase, tid);

    for (int kt = 0; kt < NKT; ++kt) {
        if (kt + 1 < NKT) {
            asm volatile("cp.async.wait_group %0;\n" :: "n"(STAGES - 2) : "memory");
        } else {
            asm volatile("cp.async.wait_group 0;\n" ::: "memory");
        }
        __syncthreads();

        const int nk = kt + STAGES - 1;
        if (nk < NKT)
            issue_stage(g_Xr, g_Wr, m0, n0, nk, nk % STAGES, sbase, tid);

        const uint32_t sA = sbase + (uint32_t)((kt % STAGES) * STAGE_FLOATS * 4);
        const uint32_t sB = sA + TILE_FLOATS * 4;

#pragma unroll
        for (int s = 0; s < TK / 8; ++s) {
            const int ks = s * 8;
            uint32_t a[2][4];
#pragma unroll
            for (int mi = 0; mi < 2; ++mi) {
                const int r = wm * 32 + mi * 16 + a_row;
                ldsm4(a[mi], sA + (uint32_t)(r * RSTRIDE + ks + a_kofs) * 4);
            }
            uint32_t bf[4][4];     // bf[j] = {b0,b1 of tile 2j, b0,b1 of tile 2j+1}
#pragma unroll
            for (int j = 0; j < 4; ++j) {
                const int r = wn * 64 + j * 16 + b_row;
                ldsm4(bf[j], sB + (uint32_t)(r * RSTRIDE + ks + b_kofs) * 4);
            }
#pragma unroll
            for (int mi = 0; mi < 2; ++mi)
#pragma unroll
                for (int ni = 0; ni < 8; ++ni)
                    mma_tf32(acc[mi][ni], a[mi], &bf[ni >> 1][(ni & 1) * 2]);
        }
    }

    // epilogue: c0=(g,nc2) c1=(g,nc2+1) c2=(g+8,nc2) c3=(g+8,nc2+1)
#pragma unroll
    for (int mi = 0; mi < 2; ++mi) {
        const int m = m0 + wm * 32 + mi * 16 + g;
#pragma unroll
        for (int ni = 0; ni < 8; ++ni) {
            const int n = n0 + wn * 64 + ni * 8 + nc2;
            const float2 bb = *(const float2*)(bias + n);
            float2 o0, o1;
            o0.x = acc[mi][ni][0] + bb.x;
            o0.y = acc[mi][ni][1] + bb.y;
            o1.x = acc[mi][ni][2] + bb.x;
            o1.y = acc[mi][ni][3] + bb.y;
            *(float2*)(out + (size_t)m * DD + n) = o0;
            *(float2*)(out + (size_t)(m + 8) * DD + n) = o1;
        }
    }
}

// ---------------------------------------------------------------------------
extern "C" void kernel_launch(void* const* d_in, const int* in_sizes, int n_in,
                              void* d_out, int out_size) {
    const float* x = (const float*)d_in[0];   // [4,2048,4096] -> M=8192
    const float* W = (const float*)d_in[1];   // [4096,4096]
    const float* b = (const float*)d_in[2];   // [4096]
    float* out = (float*)d_out;

    cudaFuncSetAttribute(gemm_tf32_kernel,
                         cudaFuncAttributeMaxDynamicSharedMemorySize, SMEM_TOTAL);

    wht_rows_kernel<<<DD, 512>>>(W);
    cvt_x_kernel<<<(MM * DD / 4) / 256, 256>>>((const float4*)x);

    const int grid = (MM / TM) * (DD / TN);   // 2048
    gemm_tf32_kernel<<<grid, 256, SMEM_TOTAL>>>(b, out);
}

// round 4
// speedup vs baseline: 2.6042x; 2.6042x over previous
#include <cuda_runtime.h>
#include <cuda_fp16.h>
#include <cstdint>
#include <cstddef>

#define DD 4096
#define MM 8192

// Scratch: Hadamard-rotated fp16 W [N,K]; fp16 x [M,K].
__device__ __align__(256) __half g_Wh[(size_t)DD * DD];
__device__ __align__(256) __half g_Xh[(size_t)MM * DD];

// ---------------------------------------------------------------------------
// Kernel 1: row-wise WHT of W, scale 1/64, round to fp16 (RN).
// (xH)W^T == x(WH)^T since H is symmetric.
// ---------------------------------------------------------------------------
__global__ void wht_rows_kernel(const float* __restrict__ W) {
    __shared__ float h[DD];
    const int row = blockIdx.x;
    const float* src = W + (size_t)row * DD;
    for (int i = threadIdx.x; i < DD; i += blockDim.x) h[i] = src[i];
    __syncthreads();
    for (int len = 1; len < DD; len <<= 1) {
        for (int p = threadIdx.x; p < DD / 2; p += blockDim.x) {
            int i = ((p & ~(len - 1)) << 1) | (p & (len - 1));
            float a = h[i], b = h[i + len];
            h[i] = a + b;
            h[i + len] = a - b;
        }
        __syncthreads();
    }
    __half* dst = g_Wh + (size_t)row * DD;
    for (int i = threadIdx.x; i < DD; i += blockDim.x)
        dst[i] = __float2half_rn(h[i] * 0.015625f);
}

// ---------------------------------------------------------------------------
// Kernel 2: round x to fp16 (RN). 8 halves per thread.
// ---------------------------------------------------------------------------
__global__ void cvt_x_kernel(const float4* __restrict__ x) {
    const size_t idx = (size_t)blockIdx.x * blockDim.x + threadIdx.x;
    float4 v0 = x[2 * idx];
    float4 v1 = x[2 * idx + 1];
    __half2 h0 = __floats2half2_rn(v0.x, v0.y);
    __half2 h1 = __floats2half2_rn(v0.z, v0.w);
    __half2 h2 = __floats2half2_rn(v1.x, v1.y);
    __half2 h3 = __floats2half2_rn(v1.z, v1.w);
    uint4 o;
    o.x = *(uint32_t*)&h0; o.y = *(uint32_t*)&h1;
    o.z = *(uint32_t*)&h2; o.w = *(uint32_t*)&h3;
    ((uint4*)g_Xh)[idx] = o;
}

// ---------------------------------------------------------------------------
// Kernel 3: fp16 mma.sync GEMM  out[M,N] = Xh[M,K] @ Wh[N,K]^T + bias
// CTA 128x256, warp tile 64x64 (2x4 warps), TK=64 halves (128B rows),
// 4-stage cp.async, XOR-swizzled smem (conflict-free ldmatrix + stores).
// ---------------------------------------------------------------------------
constexpr int TM = 128;
constexpr int TN = 256;
constexpr int TKH = 64;                      // halves per K-tile (128 B)
constexpr int NKT = DD / TKH;                // 64
constexpr int STAGES = 4;
constexpr int A_BYTES = TM * 128;            // 16384
constexpr int B_BYTES = TN * 128;            // 32768
constexpr int STAGE_BYTES = A_BYTES + B_BYTES;          // 49152
constexpr int SMEM_TOTAL = STAGES * STAGE_BYTES;        // 196608

__device__ __forceinline__ uint32_t smem_u32(const void* p) {
    return (uint32_t)__cvta_generic_to_shared(p);
}
__device__ __forceinline__ void cp16(uint32_t dst, const void* src) {
    asm volatile("cp.async.cg.shared.global [%0], [%1], 16;\n" :: "r"(dst), "l"(src));
}
__device__ __forceinline__ void ldsm4(uint32_t* r, uint32_t addr) {
    asm volatile("ldmatrix.sync.aligned.m8n8.x4.shared.b16 {%0,%1,%2,%3}, [%4];"
                 : "=r"(r[0]), "=r"(r[1]), "=r"(r[2]), "=r"(r[3]) : "r"(addr));
}
__device__ __forceinline__ void mma_f16(float* c, const uint32_t* a, const uint32_t* b) {
    asm volatile(
        "mma.sync.aligned.m16n8k16.row.col.f32.f16.f16.f32 "
        "{%0,%1,%2,%3}, {%4,%5,%6,%7}, {%8,%9}, {%0,%1,%2,%3};"
        : "+f"(c[0]), "+f"(c[1]), "+f"(c[2]), "+f"(c[3])
        : "r"(a[0]), "r"(a[1]), "r"(a[2]), "r"(a[3]),
          "r"(b[0]), "r"(b[1]));
}

// swizzled byte offset inside a tile: 128B rows, 16B chunks, chunk ^= row&7
__device__ __forceinline__ uint32_t sw_off(int row, int chunk) {
    return (uint32_t)(row * 128 + ((chunk ^ (row & 7)) << 4));
}

__device__ __forceinline__ void issue_stage(int m0, int n0, int kt, int slot,
                                            uint32_t sbase, int tid) {
    const uint32_t stA = sbase + (uint32_t)(slot * STAGE_BYTES);
    const uint32_t stB = stA + A_BYTES;
    const __half* gA = g_Xh + (size_t)m0 * DD + kt * TKH;
    const __half* gB = g_Wh + (size_t)n0 * DD + kt * TKH;
#pragma unroll
    for (int i = 0; i < 4; ++i) {            // A: 1024 16B chunks
        const int idx = tid + i * 256;
        const int row = idx >> 3;
        const int c = idx & 7;
        cp16(stA + sw_off(row, c), gA + (size_t)row * DD + c * 8);
    }
#pragma unroll
    for (int i = 0; i < 8; ++i) {            // B: 2048 16B chunks
        const int idx = tid + i * 256;
        const int row = idx >> 3;
        const int c = idx & 7;
        cp16(stB + sw_off(row, c), gB + (size_t)row * DD + c * 8);
    }
    asm volatile("cp.async.commit_group;\n" ::: "memory");
}

__global__ void __launch_bounds__(256, 1)
gemm_f16_kernel(const float* __restrict__ bias, float* __restrict__ out) {
    extern __shared__ char smem[];
    const uint32_t sbase = smem_u32(smem);
    const int tid = threadIdx.x;
    const int wid = tid >> 5;
    const int lane = tid & 31;
    const int g = lane >> 2;              // accumulator row within 8
    const int nc2 = (lane & 3) * 2;       // accumulator n-col base
    const int wm = wid & 1;               // 2 warps along M
    const int wn = wid >> 1;              // 4 warps along N

    // per-lane ldmatrix row/chunk components
    const int a_row = lane & 15;
    const int a_cofs = lane >> 4;                       // 0/1
    const int b_row = ((lane >> 4) << 3) + (lane & 7);
    const int b_cofs = (lane >> 3) & 1;                 // 0/1

    // CTA swizzle: groups of 16 M-tiles sweep all 16 N-tiles (L2 locality)
    constexpr int PN = DD / TN;           // 16
    constexpr int G = 16;
    const int pid = blockIdx.x;
    const int grp = pid / (G * PN);
    const int pm = grp * G + (pid % G);
    const int pn = (pid % (G * PN)) / G;
    const int m0 = pm * TM;
    const int n0 = pn * TN;

    float acc[4][8][4];
#pragma unroll
    for (int mi = 0; mi < 4; ++mi)
#pragma unroll
        for (int ni = 0; ni < 8; ++ni)
#pragma unroll
            for (int v = 0; v < 4; ++v) acc[mi][ni][v] = 0.0f;

#pragma unroll
    for (int kt = 0; kt < STAGES - 1; ++kt)
        issue_stage(m0, n0, kt, kt, sbase, tid);

    for (int kt = 0; kt < NKT; ++kt) {
        const int rem = NKT - 1 - kt;
        if (rem >= STAGES - 2) {
            asm volatile("cp.async.wait_group %0;\n" :: "n"(STAGES - 2) : "memory");
        } else if (rem == 1) {
            asm volatile("cp.async.wait_group 1;\n" ::: "memory");
        } else {
            asm volatile("cp.async.wait_group 0;\n" ::: "memory");
        }
        __syncthreads();

        const int nk = kt + STAGES - 1;
        if (nk < NKT)
            issue_stage(m0, n0, nk, nk % STAGES, sbase, tid);

        const uint32_t sA = sbase + (uint32_t)((kt % STAGES) * STAGE_BYTES);
        const uint32_t sB = sA + A_BYTES;

#pragma unroll
        for (int s = 0; s < TKH / 16; ++s) {   // 4 k16 steps
            uint32_t a[4][4];
#pragma unroll
            for (int mi = 0; mi < 4; ++mi) {
                const int r = wm * 64 + mi * 16 + a_row;
                ldsm4(a[mi], sA + sw_off(r, 2 * s + a_cofs));
            }
            uint32_t bf[4][4];   // bf[j] = {b0,b1 tile 2j, b0,b1 tile 2j+1}
#pragma unroll
            for (int j = 0; j < 4; ++j) {
                const int r = wn * 64 + j * 16 + b_row;
                ldsm4(bf[j], sB + sw_off(r, 2 * s + b_cofs));
            }
#pragma unroll
            for (int mi = 0; mi < 4; ++mi)
#pragma unroll
                for (int ni = 0; ni < 8; ++ni)
                    mma_f16(acc[mi][ni], a[mi], &bf[ni >> 1][(ni & 1) * 2]);
        }
    }

    // epilogue
#pragma unroll
    for (int mi = 0; mi < 4; ++mi) {
        const int m = m0 + wm * 64 + mi * 16 + g;
#pragma unroll
        for (int ni = 0; ni < 8; ++ni) {
            const int n = n0 + wn * 64 + ni * 8 + nc2;
            const float2 bb = *(const float2*)(bias + n);
            float2 o0, o1;
            o0.x = acc[mi][ni][0] + bb.x;
            o0.y = acc[mi][ni][1] + bb.y;
            o1.x = acc[mi][ni][2] + bb.x;
            o1.y = acc[mi][ni][3] + bb.y;
            *(float2*)(out + (size_t)m * DD + n) = o0;
            *(float2*)(out + (size_t)(m + 8) * DD + n) = o1;
        }
    }
}

// ---------------------------------------------------------------------------
extern "C" void kernel_launch(void* const* d_in, const int* in_sizes, int n_in,
                              void* d_out, int out_size) {
    const float* x = (const float*)d_in[0];   // [4,2048,4096] -> M=8192
    const float* W = (const float*)d_in[1];   // [4096,4096]
    const float* b = (const float*)d_in[2];   // [4096]
    float* out = (float*)d_out;

    cudaFuncSetAttribute(gemm_f16_kernel,
                         cudaFuncAttributeMaxDynamicSharedMemorySize, SMEM_TOTAL);

    wht_rows_kernel<<<DD, 512>>>(W);
    cvt_x_kernel<<<(MM * DD / 8) / 256, 256>>>((const float4*)x);

    const int grid = (MM / TM) * (DD / TN);   // 64 * 16 = 1024
    gemm_f16_kernel<<<grid, 256, SMEM_TOTAL>>>(b, out);
}

// round 5
// speedup vs baseline: 2.7120x; 1.0414x over previous
#include <cuda_runtime.h>
#include <cuda_fp16.h>
#include <cstdint>
#include <cstddef>

#define DD 4096
#define MM 8192

// Scratch: Hadamard-rotated fp16 W [N,K]; fp16 x [M,K].
__device__ __align__(256) __half g_Wh[(size_t)DD * DD];
__device__ __align__(256) __half g_Xh[(size_t)MM * DD];

// ---------------------------------------------------------------------------
// Kernel 1 (fused prep):
//   blocks [0, 4096):     row-wise WHT of W, scale 1/64, round fp16
//   blocks [4096, 8192):  convert x to fp16
// (xH)W^T == x(WH)^T since H is symmetric.
// ---------------------------------------------------------------------------
__global__ void prep_kernel(const float* __restrict__ W,
                            const float4* __restrict__ x) {
    if (blockIdx.x < DD) {
        __shared__ float h[DD];
        const int row = blockIdx.x;
        const float* src = W + (size_t)row * DD;
        for (int i = threadIdx.x; i < DD; i += blockDim.x) h[i] = src[i];
        __syncthreads();
        for (int len = 1; len < DD; len <<= 1) {
            for (int p = threadIdx.x; p < DD / 2; p += blockDim.x) {
                int i = ((p & ~(len - 1)) << 1) | (p & (len - 1));
                float a = h[i], b = h[i + len];
                h[i] = a + b;
                h[i + len] = a - b;
            }
            __syncthreads();
        }
        __half* dst = g_Wh + (size_t)row * DD;
        for (int i = threadIdx.x; i < DD; i += blockDim.x)
            dst[i] = __float2half_rn(h[i] * 0.015625f);
    } else {
        // 4096 blocks x 512 threads x 2 uint4-out (16 floats) = MM*DD
        const size_t base = ((size_t)(blockIdx.x - DD) * blockDim.x + threadIdx.x) * 2;
#pragma unroll
        for (int u = 0; u < 2; ++u) {
            const size_t idx = base + u;
            float4 v0 = x[2 * idx];
            float4 v1 = x[2 * idx + 1];
            __half2 h0 = __floats2half2_rn(v0.x, v0.y);
            __half2 h1 = __floats2half2_rn(v0.z, v0.w);
            __half2 h2 = __floats2half2_rn(v1.x, v1.y);
            __half2 h3 = __floats2half2_rn(v1.z, v1.w);
            uint4 o;
            o.x = *(uint32_t*)&h0; o.y = *(uint32_t*)&h1;
            o.z = *(uint32_t*)&h2; o.w = *(uint32_t*)&h3;
            ((uint4*)g_Xh)[idx] = o;
        }
    }
}

// ---------------------------------------------------------------------------
// Kernel 2: fp16 mma.sync GEMM  out[M,N] = Xh[M,K] @ Wh[N,K]^T + bias
// CTA 128x256, 16 warps (4x4), warp tile 32x64, TK=64 halves (128B rows),
// 4-stage cp.async, XOR-swizzled smem (conflict-free ldmatrix + stores).
// ---------------------------------------------------------------------------
constexpr int TM = 128;
constexpr int TN = 256;
constexpr int TKH = 64;                      // halves per K-tile (128 B)
constexpr int NKT = DD / TKH;                // 64
constexpr int STAGES = 4;
constexpr int A_BYTES = TM * 128;            // 16384
constexpr int B_BYTES = TN * 128;            // 32768
constexpr int STAGE_BYTES = A_BYTES + B_BYTES;          // 49152
constexpr int SMEM_TOTAL = STAGES * STAGE_BYTES;        // 196608
constexpr int NTHREADS = 512;

__device__ __forceinline__ uint32_t smem_u32(const void* p) {
    return (uint32_t)__cvta_generic_to_shared(p);
}
__device__ __forceinline__ void cp16(uint32_t dst, const void* src) {
    asm volatile("cp.async.cg.shared.global [%0], [%1], 16;\n" :: "r"(dst), "l"(src));
}
__device__ __forceinline__ void ldsm4(uint32_t* r, uint32_t addr) {
    asm volatile("ldmatrix.sync.aligned.m8n8.x4.shared.b16 {%0,%1,%2,%3}, [%4];"
                 : "=r"(r[0]), "=r"(r[1]), "=r"(r[2]), "=r"(r[3]) : "r"(addr));
}
__device__ __forceinline__ void mma_f16(float* c, const uint32_t* a, const uint32_t* b) {
    asm volatile(
        "mma.sync.aligned.m16n8k16.row.col.f32.f16.f16.f32 "
        "{%0,%1,%2,%3}, {%4,%5,%6,%7}, {%8,%9}, {%0,%1,%2,%3};"
        : "+f"(c[0]), "+f"(c[1]), "+f"(c[2]), "+f"(c[3])
        : "r"(a[0]), "r"(a[1]), "r"(a[2]), "r"(a[3]),
          "r"(b[0]), "r"(b[1]));
}

// swizzled byte offset inside a tile: 128B rows, 16B chunks, chunk ^= row&7
__device__ __forceinline__ uint32_t sw_off(int row, int chunk) {
    return (uint32_t)(row * 128 + ((chunk ^ (row & 7)) << 4));
}

__device__ __forceinline__ void issue_stage(int m0, int n0, int kt, int slot,
                                            uint32_t sbase, int tid) {
    const uint32_t stA = sbase + (uint32_t)(slot * STAGE_BYTES);
    const uint32_t stB = stA + A_BYTES;
    const __half* gA = g_Xh + (size_t)m0 * DD + kt * TKH;
    const __half* gB = g_Wh + (size_t)n0 * DD + kt * TKH;
#pragma unroll
    for (int i = 0; i < 2; ++i) {            // A: 1024 16B chunks
        const int idx = tid + i * NTHREADS;
        const int row = idx >> 3;
        const int c = idx & 7;
        cp16(stA + sw_off(row, c), gA + (size_t)row * DD + c * 8);
    }
#pragma unroll
    for (int i = 0; i < 4; ++i) {            // B: 2048 16B chunks
        const int idx = tid + i * NTHREADS;
        const int row = idx >> 3;
        const int c = idx & 7;
        cp16(stB + sw_off(row, c), gB + (size_t)row * DD + c * 8);
    }
    asm volatile("cp.async.commit_group;\n" ::: "memory");
}

__global__ void __launch_bounds__(NTHREADS, 1)
gemm_f16_kernel(const float* __restrict__ bias, float* __restrict__ out) {
    extern __shared__ char smem[];
    const uint32_t sbase = smem_u32(smem);
    const int tid = threadIdx.x;
    const int wid = tid >> 5;
    const int lane = tid & 31;
    const int g = lane >> 2;              // accumulator row within 8
    const int nc2 = (lane & 3) * 2;       // accumulator n-col base
    const int wm = wid & 3;               // 4 warps along M (32 rows each)
    const int wn = wid >> 2;              // 4 warps along N (64 cols each)

    // per-lane ldmatrix row/chunk components
    const int a_row = lane & 15;
    const int a_cofs = lane >> 4;                       // 0/1
    const int b_row = ((lane >> 4) << 3) + (lane & 7);
    const int b_cofs = (lane >> 3) & 1;                 // 0/1

    // CTA swizzle: groups of 16 M-tiles sweep all 16 N-tiles (L2 locality)
    constexpr int PN = DD / TN;           // 16
    constexpr int G = 16;
    const int pid = blockIdx.x;
    const int grp = pid / (G * PN);
    const int pm = grp * G + (pid % G);
    const int pn = (pid % (G * PN)) / G;
    const int m0 = pm * TM;
    const int n0 = pn * TN;

    float acc[2][8][4];
#pragma unroll
    for (int mi = 0; mi < 2; ++mi)
#pragma unroll
        for (int ni = 0; ni < 8; ++ni)
#pragma unroll
            for (int v = 0; v < 4; ++v) acc[mi][ni][v] = 0.0f;

#pragma unroll
    for (int kt = 0; kt < STAGES - 1; ++kt)
        issue_stage(m0, n0, kt, kt, sbase, tid);

    for (int kt = 0; kt < NKT; ++kt) {
        const int rem = NKT - 1 - kt;
        if (rem >= STAGES - 2) {
            asm volatile("cp.async.wait_group %0;\n" :: "n"(STAGES - 2) : "memory");
        } else if (rem == 1) {
            asm volatile("cp.async.wait_group 1;\n" ::: "memory");
        } else {
            asm volatile("cp.async.wait_group 0;\n" ::: "memory");
        }
        __syncthreads();

        const int nk = kt + STAGES - 1;
        if (nk < NKT)
            issue_stage(m0, n0, nk, nk % STAGES, sbase, tid);

        const uint32_t sA = sbase + (uint32_t)((kt % STAGES) * STAGE_BYTES);
        const uint32_t sB = sA + A_BYTES;

#pragma unroll
        for (int s = 0; s < TKH / 16; ++s) {   // 4 k16 steps
            uint32_t a[2][4];
#pragma unroll
            for (int mi = 0; mi < 2; ++mi) {
                const int r = wm * 32 + mi * 16 + a_row;
                ldsm4(a[mi], sA + sw_off(r, 2 * s + a_cofs));
            }
            uint32_t bf[4][4];   // bf[j] = {b0,b1 tile 2j, b0,b1 tile 2j+1}
#pragma unroll
            for (int j = 0; j < 4; ++j) {
                const int r = wn * 64 + j * 16 + b_row;
                ldsm4(bf[j], sB + sw_off(r, 2 * s + b_cofs));
            }
#pragma unroll
            for (int mi = 0; mi < 2; ++mi)
#pragma unroll
                for (int ni = 0; ni < 8; ++ni)
                    mma_f16(acc[mi][ni], a[mi], &bf[ni >> 1][(ni & 1) * 2]);
        }
    }

    // epilogue
#pragma unroll
    for (int mi = 0; mi < 2; ++mi) {
        const int m = m0 + wm * 32 + mi * 16 + g;
#pragma unroll
        for (int ni = 0; ni < 8; ++ni) {
            const int n = n0 + wn * 64 + ni * 8 + nc2;
            const float2 bb = *(const float2*)(bias + n);
            float2 o0, o1;
            o0.x = acc[mi][ni][0] + bb.x;
            o0.y = acc[mi][ni][1] + bb.y;
            o1.x = acc[mi][ni][2] + bb.x;
            o1.y = acc[mi][ni][3] + bb.y;
            *(float2*)(out + (size_t)m * DD + n) = o0;
            *(float2*)(out + (size_t)(m + 8) * DD + n) = o1;
        }
    }
}

// ---------------------------------------------------------------------------
extern "C" void kernel_launch(void* const* d_in, const int* in_sizes, int n_in,
                              void* d_out, int out_size) {
    const float* x = (const float*)d_in[0];   // [4,2048,4096] -> M=8192
    const float* W = (const float*)d_in[1];   // [4096,4096]
    const float* b = (const float*)d_in[2];   // [4096]
    float* out = (float*)d_out;

    cudaFuncSetAttribute(gemm_f16_kernel,
                         cudaFuncAttributeMaxDynamicSharedMemorySize, SMEM_TOTAL);

    prep_kernel<<<2 * DD, 512>>>(W, (const float4*)x);

    const int grid = (MM / TM) * (DD / TN);   // 64 * 16 = 1024
    gemm_f16_kernel<<<grid, NTHREADS, SMEM_TOTAL>>>(b, out);
}

// round 6
// speedup vs baseline: 2.8007x; 1.0327x over previous
#include <cuda_runtime.h>
#include <cuda_fp16.h>
#include <cstdint>
#include <cstddef>

#define DD 4096
#define MM 8192

// Scratch: Hadamard-rotated fp16 W [N,K]; fp16 x [M,K].
__device__ __align__(256) __half g_Wh[(size_t)DD * DD];
__device__ __align__(256) __half g_Xh[(size_t)MM * DD];

// ---------------------------------------------------------------------------
// Kernel 1 (fused prep):
//   blocks [0, 4096):     row-wise WHT of W (reg+shuffle+smem), /64, fp16
//   blocks [4096, 8192):  convert x to fp16
// (xH)W^T == x(WH)^T since H is symmetric.
// ---------------------------------------------------------------------------
__global__ void prep_kernel(const float* __restrict__ W,
                            const float4* __restrict__ x) {
    if (blockIdx.x < DD) {
        __shared__ float sh[DD];
        const int t = threadIdx.x;          // 512 threads
        const int lane = t & 31;
        const int w = t >> 5;
        const float4* src = (const float4*)(W + (size_t)blockIdx.x * DD) + t * 2;
        float v[8];
        {
            float4 u0 = src[0], u1 = src[1];
            v[0] = u0.x; v[1] = u0.y; v[2] = u0.z; v[3] = u0.w;
            v[4] = u1.x; v[5] = u1.y; v[6] = u1.z; v[7] = u1.w;
        }
        // stages len=1,2,4: in registers
#pragma unroll
        for (int len = 1; len <= 4; len <<= 1) {
#pragma unroll
            for (int e = 0; e < 8; ++e) {
                if ((e & len) == 0) {
                    float a = v[e], b = v[e | len];
                    v[e] = a + b;
                    v[e | len] = a - b;
                }
            }
        }
        // stages len=8..128: shfl.bfly, mask = len/8
#pragma unroll
        for (int m = 1; m <= 16; m <<= 1) {
#pragma unroll
            for (int e = 0; e < 8; ++e) {
                float r = __shfl_xor_sync(0xffffffffu, v[e], m);
                v[e] = (lane & m) ? (r - v[e]) : (v[e] + r);
            }
        }
        // stages len=256..2048: cross-warp via smem
#pragma unroll
        for (int mw = 1; mw <= 8; mw <<= 1) {
            __syncthreads();
#pragma unroll
            for (int e = 0; e < 8; ++e) sh[t * 8 + e] = v[e];
            __syncthreads();
            const int p = (t ^ (mw * 32)) * 8;
#pragma unroll
            for (int e = 0; e < 8; ++e) {
                float r = sh[p + e];
                v[e] = (w & mw) ? (r - v[e]) : (v[e] + r);
            }
        }
        __half2 h[4];
#pragma unroll
        for (int e = 0; e < 4; ++e)
            h[e] = __floats2half2_rn(v[2 * e] * 0.015625f, v[2 * e + 1] * 0.015625f);
        uint4 o;
        o.x = *(uint32_t*)&h[0]; o.y = *(uint32_t*)&h[1];
        o.z = *(uint32_t*)&h[2]; o.w = *(uint32_t*)&h[3];
        *((uint4*)(g_Wh + (size_t)blockIdx.x * DD) + t) = o;
    } else {
        const size_t base = ((size_t)(blockIdx.x - DD) * blockDim.x + threadIdx.x) * 2;
#pragma unroll
        for (int u = 0; u < 2; ++u) {
            const size_t idx = base + u;
            float4 v0 = x[2 * idx];
            float4 v1 = x[2 * idx + 1];
            __half2 h0 = __floats2half2_rn(v0.x, v0.y);
            __half2 h1 = __floats2half2_rn(v0.z, v0.w);
            __half2 h2 = __floats2half2_rn(v1.x, v1.y);
            __half2 h3 = __floats2half2_rn(v1.z, v1.w);
            uint4 o;
            o.x = *(uint32_t*)&h0; o.y = *(uint32_t*)&h1;
            o.z = *(uint32_t*)&h2; o.w = *(uint32_t*)&h3;
            ((uint4*)g_Xh)[idx] = o;
        }
    }
}

// ---------------------------------------------------------------------------
// Kernel 2: fp16 mma.sync GEMM  out[M,N] = Xh[M,K] @ Wh[N,K]^T + bias
// CTA 128x256, 16 warps (4x4), warp tile 32x64, TKH=128 halves (256B rows
// stored as 2 swizzled 128B sub-tiles), 2-stage double buffer (96KB/stage).
// ---------------------------------------------------------------------------
constexpr int TM = 128;
constexpr int TN = 256;
constexpr int TKH = 128;                     // halves per K-tile (256 B)
constexpr int NKT = DD / TKH;                // 32
constexpr int A_BYTES = TM * 256;            // 32768
constexpr int B_BYTES = TN * 256;            // 65536
constexpr int A_SUB = TM * 128;              // 16384 (one 128B-chunk column)
constexpr int B_SUB = TN * 128;              // 32768
constexpr int STAGE_BYTES = A_BYTES + B_BYTES;          // 98304
constexpr int SMEM_TOTAL = 2 * STAGE_BYTES;             // 196608
constexpr int NTHREADS = 512;

__device__ __forceinline__ uint32_t smem_u32(const void* p) {
    return (uint32_t)__cvta_generic_to_shared(p);
}
__device__ __forceinline__ void cp16(uint32_t dst, const void* src) {
    asm volatile("cp.async.cg.shared.global [%0], [%1], 16;\n" :: "r"(dst), "l"(src));
}
__device__ __forceinline__ void ldsm4(uint32_t* r, uint32_t addr) {
    asm volatile("ldmatrix.sync.aligned.m8n8.x4.shared.b16 {%0,%1,%2,%3}, [%4];"
                 : "=r"(r[0]), "=r"(r[1]), "=r"(r[2]), "=r"(r[3]) : "r"(addr));
}
__device__ __forceinline__ void mma_f16(float* c, const uint32_t* a, const uint32_t* b) {
    asm volatile(
        "mma.sync.aligned.m16n8k16.row.col.f32.f16.f16.f32 "
        "{%0,%1,%2,%3}, {%4,%5,%6,%7}, {%8,%9}, {%0,%1,%2,%3};"
        : "+f"(c[0]), "+f"(c[1]), "+f"(c[2]), "+f"(c[3])
        : "r"(a[0]), "r"(a[1]), "r"(a[2]), "r"(a[3]),
          "r"(b[0]), "r"(b[1]));
}

// swizzled byte offset inside one 128B-wide sub-tile
__device__ __forceinline__ uint32_t sw_off(int row, int chunk) {
    return (uint32_t)(row * 128 + ((chunk ^ (row & 7)) << 4));
}

__device__ __forceinline__ void issue_stage(int m0, int n0, int kt, int slot,
                                            uint32_t sbase, int tid) {
    const uint32_t stA = sbase + (uint32_t)(slot * STAGE_BYTES);
    const uint32_t stB = stA + A_BYTES;
    const __half* gA = g_Xh + (size_t)m0 * DD + kt * TKH;
    const __half* gB = g_Wh + (size_t)n0 * DD + kt * TKH;
#pragma unroll
    for (int i = 0; i < 4; ++i) {            // A: 2048 16B chunks
        const int idx = tid + i * NTHREADS;
        const int row = idx >> 4;
        const int c = idx & 15;
        cp16(stA + (c >> 3) * A_SUB + sw_off(row, c & 7),
             gA + (size_t)row * DD + c * 8);
    }
#pragma unroll
    for (int i = 0; i < 8; ++i) {            // B: 4096 16B chunks
        const int idx = tid + i * NTHREADS;
        const int row = idx >> 4;
        const int c = idx & 15;
        cp16(stB + (c >> 3) * B_SUB + sw_off(row, c & 7),
             gB + (size_t)row * DD + c * 8);
    }
    asm volatile("cp.async.commit_group;\n" ::: "memory");
}

__global__ void __launch_bounds__(NTHREADS, 1)
gemm_f16_kernel(const float* __restrict__ bias, float* __restrict__ out) {
    extern __shared__ char smem[];
    const uint32_t sbase = smem_u32(smem);
    const int tid = threadIdx.x;
    const int wid = tid >> 5;
    const int lane = tid & 31;
    const int g = lane >> 2;              // accumulator row within 8
    const int nc2 = (lane & 3) * 2;       // accumulator n-col base
    const int wm = wid & 3;               // 4 warps along M (32 rows each)
    const int wn = wid >> 2;              // 4 warps along N (64 cols each)

    // per-lane ldmatrix row/chunk components
    const int a_row = lane & 15;
    const int a_cofs = lane >> 4;                       // 0/1
    const int b_row = ((lane >> 4) << 3) + (lane & 7);
    const int b_cofs = (lane >> 3) & 1;                 // 0/1

    // CTA swizzle: groups of 16 M-tiles sweep all 16 N-tiles (L2 locality)
    constexpr int PN = DD / TN;           // 16
    constexpr int G = 16;
    const int pid = blockIdx.x;
    const int grp = pid / (G * PN);
    const int pm = grp * G + (pid % G);
    const int pn = (pid % (G * PN)) / G;
    const int m0 = pm * TM;
    const int n0 = pn * TN;

    float acc[2][8][4];
#pragma unroll
    for (int mi = 0; mi < 2; ++mi)
#pragma unroll
        for (int ni = 0; ni < 8; ++ni)
#pragma unroll
            for (int v = 0; v < 4; ++v) acc[mi][ni][v] = 0.0f;

    issue_stage(m0, n0, 0, 0, sbase, tid);

    for (int kt = 0; kt < NKT; ++kt) {
        if (kt + 1 < NKT) {
            issue_stage(m0, n0, kt + 1, (kt + 1) & 1, sbase, tid);
            asm volatile("cp.async.wait_group 1;\n" ::: "memory");
        } else {
            asm volatile("cp.async.wait_group 0;\n" ::: "memory");
        }
        __syncthreads();

        const uint32_t sA = sbase + (uint32_t)((kt & 1) * STAGE_BYTES);
        const uint32_t sB = sA + A_BYTES;

#pragma unroll
        for (int s = 0; s < TKH / 16; ++s) {   // 8 k16 steps
            const int ca = 2 * s + a_cofs;     // chunk index 0..15
            const int cb = 2 * s + b_cofs;
            uint32_t a[2][4];
#pragma unroll
            for (int mi = 0; mi < 2; ++mi) {
                const int r = wm * 32 + mi * 16 + a_row;
                ldsm4(a[mi], sA + (ca >> 3) * A_SUB + sw_off(r, ca & 7));
            }
            uint32_t bf[4][4];   // bf[j] = {b0,b1 tile 2j, b0,b1 tile 2j+1}
#pragma unroll
            for (int j = 0; j < 4; ++j) {
                const int r = wn * 64 + j * 16 + b_row;
                ldsm4(bf[j], sB + (cb >> 3) * B_SUB + sw_off(r, cb & 7));
            }
#pragma unroll
            for (int mi = 0; mi < 2; ++mi)
#pragma unroll
                for (int ni = 0; ni < 8; ++ni)
                    mma_f16(acc[mi][ni], a[mi], &bf[ni >> 1][(ni & 1) * 2]);
        }
        __syncthreads();   // reads of this slot done before it is re-filled
    }

    // epilogue
#pragma unroll
    for (int mi = 0; mi < 2; ++mi) {
        const int m = m0 + wm * 32 + mi * 16 + g;
#pragma unroll
        for (int ni = 0; ni < 8; ++ni) {
            const int n = n0 + wn * 64 + ni * 8 + nc2;
            const float2 bb = *(const float2*)(bias + n);
            float2 o0, o1;
            o0.x = acc[mi][ni][0] + bb.x;
            o0.y = acc[mi][ni][1] + bb.y;
            o1.x = acc[mi][ni][2] + bb.x;
            o1.y = acc[mi][ni][3] + bb.y;
            *(float2*)(out + (size_t)m * DD + n) = o0;
            *(float2*)(out + (size_t)(m + 8) * DD + n) = o1;
        }
    }
}

// ---------------------------------------------------------------------------
extern "C" void kernel_launch(void* const* d_in, const int* in_sizes, int n_in,
                              void* d_out, int out_size) {
    const float* x = (const float*)d_in[0];   // [4,2048,4096] -> M=8192
    const float* W = (const float*)d_in[1];   // [4096,4096]
    const float* b = (const float*)d_in[2];   // [4096]
    float* out = (float*)d_out;

    cudaFuncSetAttribute(gemm_f16_kernel,
                         cudaFuncAttributeMaxDynamicSharedMemorySize, SMEM_TOTAL);

    prep_kernel<<<2 * DD, 512>>>(W, (const float4*)x);

    const int grid = (MM / TM) * (DD / TN);   // 64 * 16 = 1024
    gemm_f16_kernel<<<grid, NTHREADS, SMEM_TOTAL>>>(b, out);
}

// round 7
// speedup vs baseline: 2.8783x; 1.0277x over previous
#include <cuda_runtime.h>
#include <cuda_fp16.h>
#include <cstdint>
#include <cstddef>

#define DD 4096
#define MM 8192

// Scratch: Hadamard-rotated fp16 W [N,K]; fp16 x [M,K].
__device__ __align__(256) __half g_Wh[(size_t)DD * DD];
__device__ __align__(256) __half g_Xh[(size_t)MM * DD];

// ---------------------------------------------------------------------------
// Kernel 1 (fused prep):
//   blocks [0, 4096):     row-wise WHT of W (reg+shuffle+smem), /64, fp16
//   blocks [4096, 8192):  convert x to fp16
// (xH)W^T == x(WH)^T since H is symmetric.
// ---------------------------------------------------------------------------
__global__ void prep_kernel(const float* __restrict__ W,
                            const float4* __restrict__ x) {
    if (blockIdx.x < DD) {
        __shared__ float sh[DD];
        const int t = threadIdx.x;          // 512 threads
        const int lane = t & 31;
        const int w = t >> 5;
        const float4* src = (const float4*)(W + (size_t)blockIdx.x * DD) + t * 2;
        float v[8];
        {
            float4 u0 = src[0], u1 = src[1];
            v[0] = u0.x; v[1] = u0.y; v[2] = u0.z; v[3] = u0.w;
            v[4] = u1.x; v[5] = u1.y; v[6] = u1.z; v[7] = u1.w;
        }
#pragma unroll
        for (int len = 1; len <= 4; len <<= 1) {
#pragma unroll
            for (int e = 0; e < 8; ++e) {
                if ((e & len) == 0) {
                    float a = v[e], b = v[e | len];
                    v[e] = a + b;
                    v[e | len] = a - b;
                }
            }
        }
#pragma unroll
        for (int m = 1; m <= 16; m <<= 1) {
#pragma unroll
            for (int e = 0; e < 8; ++e) {
                float r = __shfl_xor_sync(0xffffffffu, v[e], m);
                v[e] = (lane & m) ? (r - v[e]) : (v[e] + r);
            }
        }
#pragma unroll
        for (int mw = 1; mw <= 8; mw <<= 1) {
            __syncthreads();
#pragma unroll
            for (int e = 0; e < 8; ++e) sh[t * 8 + e] = v[e];
            __syncthreads();
            const int p = (t ^ (mw * 32)) * 8;
#pragma unroll
            for (int e = 0; e < 8; ++e) {
                float r = sh[p + e];
                v[e] = (w & mw) ? (r - v[e]) : (v[e] + r);
            }
        }
        __half2 h[4];
#pragma unroll
        for (int e = 0; e < 4; ++e)
            h[e] = __floats2half2_rn(v[2 * e] * 0.015625f, v[2 * e + 1] * 0.015625f);
        uint4 o;
        o.x = *(uint32_t*)&h[0]; o.y = *(uint32_t*)&h[1];
        o.z = *(uint32_t*)&h[2]; o.w = *(uint32_t*)&h[3];
        *((uint4*)(g_Wh + (size_t)blockIdx.x * DD) + t) = o;
    } else {
        const size_t base = ((size_t)(blockIdx.x - DD) * blockDim.x + threadIdx.x) * 2;
#pragma unroll
        for (int u = 0; u < 2; ++u) {
            const size_t idx = base + u;
            float4 v0 = x[2 * idx];
            float4 v1 = x[2 * idx + 1];
            __half2 h0 = __floats2half2_rn(v0.x, v0.y);
            __half2 h1 = __floats2half2_rn(v0.z, v0.w);
            __half2 h2 = __floats2half2_rn(v1.x, v1.y);
            __half2 h3 = __floats2half2_rn(v1.z, v1.w);
            uint4 o;
            o.x = *(uint32_t*)&h0; o.y = *(uint32_t*)&h1;
            o.z = *(uint32_t*)&h2; o.w = *(uint32_t*)&h3;
            ((uint4*)g_Xh)[idx] = o;
        }
    }
}

// ---------------------------------------------------------------------------
// Kernel 2: fp16 mma.sync GEMM  out[M,N] = Xh[M,K] @ Wh[N,K]^T + bias
// CTA 128x128, 8 warps (2x4), warp tile 64x32, TKH=64 (128B rows),
// 3-stage cp.async, XOR-swizzled smem. TWO CTAs per SM (desynchronized
// barriers keep the tensor pipe fed during each other's sync/refill).
// ---------------------------------------------------------------------------
constexpr int TM = 128;
constexpr int TN = 128;
constexpr int TKH = 64;                      // halves per K-tile (128 B)
constexpr int NKT = DD / TKH;                // 64
constexpr int STAGES = 3;
constexpr int A_BYTES = TM * 128;            // 16384
constexpr int B_BYTES = TN * 128;            // 16384
constexpr int STAGE_BYTES = A_BYTES + B_BYTES;          // 32768
constexpr int SMEM_TOTAL = STAGES * STAGE_BYTES;        // 98304
constexpr int NTHREADS = 256;

__device__ __forceinline__ uint32_t smem_u32(const void* p) {
    return (uint32_t)__cvta_generic_to_shared(p);
}
__device__ __forceinline__ void cp16(uint32_t dst, const void* src) {
    asm volatile("cp.async.cg.shared.global [%0], [%1], 16;\n" :: "r"(dst), "l"(src));
}
__device__ __forceinline__ void ldsm4(uint32_t* r, uint32_t addr) {
    asm volatile("ldmatrix.sync.aligned.m8n8.x4.shared.b16 {%0,%1,%2,%3}, [%4];"
                 : "=r"(r[0]), "=r"(r[1]), "=r"(r[2]), "=r"(r[3]) : "r"(addr));
}
__device__ __forceinline__ void mma_f16(float* c, const uint32_t* a, const uint32_t* b) {
    asm volatile(
        "mma.sync.aligned.m16n8k16.row.col.f32.f16.f16.f32 "
        "{%0,%1,%2,%3}, {%4,%5,%6,%7}, {%8,%9}, {%0,%1,%2,%3};"
        : "+f"(c[0]), "+f"(c[1]), "+f"(c[2]), "+f"(c[3])
        : "r"(a[0]), "r"(a[1]), "r"(a[2]), "r"(a[3]),
          "r"(b[0]), "r"(b[1]));
}

// swizzled byte offset inside a 128B-wide tile
__device__ __forceinline__ uint32_t sw_off(int row, int chunk) {
    return (uint32_t)(row * 128 + ((chunk ^ (row & 7)) << 4));
}

__device__ __forceinline__ void issue_stage(int m0, int n0, int kt, int slot,
                                            uint32_t sbase, int tid) {
    const uint32_t stA = sbase + (uint32_t)(slot * STAGE_BYTES);
    const uint32_t stB = stA + A_BYTES;
    const __half* gA = g_Xh + (size_t)m0 * DD + kt * TKH;
    const __half* gB = g_Wh + (size_t)n0 * DD + kt * TKH;
#pragma unroll
    for (int i = 0; i < 4; ++i) {            // A: 1024 16B chunks
        const int idx = tid + i * NTHREADS;
        const int row = idx >> 3;
        const int c = idx & 7;
        cp16(stA + sw_off(row, c), gA + (size_t)row * DD + c * 8);
    }
#pragma unroll
    for (int i = 0; i < 4; ++i) {            // B: 1024 16B chunks
        const int idx = tid + i * NTHREADS;
        const int row = idx >> 3;
        const int c = idx & 7;
        cp16(stB + sw_off(row, c), gB + (size_t)row * DD + c * 8);
    }
    asm volatile("cp.async.commit_group;\n" ::: "memory");
}

__global__ void __launch_bounds__(NTHREADS, 2)
gemm_f16_kernel(const float* __restrict__ bias, float* __restrict__ out) {
    extern __shared__ char smem[];
    const uint32_t sbase = smem_u32(smem);
    const int tid = threadIdx.x;
    const int wid = tid >> 5;
    const int lane = tid & 31;
    const int g = lane >> 2;              // accumulator row within 8
    const int nc2 = (lane & 3) * 2;       // accumulator n-col base
    const int wm = wid & 1;               // 2 warps along M (64 rows each)
    const int wn = wid >> 1;              // 4 warps along N (32 cols each)

    // per-lane ldmatrix row/chunk components
    const int a_row = lane & 15;
    const int a_cofs = lane >> 4;                       // 0/1
    const int b_row = ((lane >> 4) << 3) + (lane & 7);
    const int b_cofs = (lane >> 3) & 1;                 // 0/1

    // CTA swizzle: groups of 16 M-tiles sweep all 32 N-tiles (L2 locality)
    constexpr int PN = DD / TN;           // 32
    constexpr int G = 16;
    const int pid = blockIdx.x;
    const int grp = pid / (G * PN);
    const int pm = grp * G + (pid % G);
    const int pn = (pid % (G * PN)) / G;
    const int m0 = pm * TM;
    const int n0 = pn * TN;

    float acc[4][4][4];
#pragma unroll
    for (int mi = 0; mi < 4; ++mi)
#pragma unroll
        for (int ni = 0; ni < 4; ++ni)
#pragma unroll
            for (int v = 0; v < 4; ++v) acc[mi][ni][v] = 0.0f;

#pragma unroll
    for (int kt = 0; kt < STAGES - 1; ++kt)
        issue_stage(m0, n0, kt, kt, sbase, tid);

    for (int kt = 0; kt < NKT; ++kt) {
        const int rem = NKT - 1 - kt;
        if (rem >= STAGES - 2) {
            asm volatile("cp.async.wait_group %0;\n" :: "n"(STAGES - 2) : "memory");
        } else {
            asm volatile("cp.async.wait_group 0;\n" ::: "memory");
        }
        __syncthreads();

        const int nk = kt + STAGES - 1;
        if (nk < NKT)
            issue_stage(m0, n0, nk, nk % STAGES, sbase, tid);

        const uint32_t sA = sbase + (uint32_t)((kt % STAGES) * STAGE_BYTES);
        const uint32_t sB = sA + A_BYTES;

#pragma unroll
        for (int s = 0; s < TKH / 16; ++s) {   // 4 k16 steps
            uint32_t a[4][4];
#pragma unroll
            for (int mi = 0; mi < 4; ++mi) {
                const int r = wm * 64 + mi * 16 + a_row;
                ldsm4(a[mi], sA + sw_off(r, 2 * s + a_cofs));
            }
            uint32_t bf[2][4];   // bf[j] = {b0,b1 tile 2j, b0,b1 tile 2j+1}
#pragma unroll
            for (int j = 0; j < 2; ++j) {
                const int r = wn * 32 + j * 16 + b_row;
                ldsm4(bf[j], sB + sw_off(r, 2 * s + b_cofs));
            }
#pragma unroll
            for (int mi = 0; mi < 4; ++mi)
#pragma unroll
                for (int ni = 0; ni < 4; ++ni)
                    mma_f16(acc[mi][ni], a[mi], &bf[ni >> 1][(ni & 1) * 2]);
        }
    }

    // epilogue
#pragma unroll
    for (int mi = 0; mi < 4; ++mi) {
        const int m = m0 + wm * 64 + mi * 16 + g;
#pragma unroll
        for (int ni = 0; ni < 4; ++ni) {
            const int n = n0 + wn * 32 + ni * 8 + nc2;
            const float2 bb = *(const float2*)(bias + n);
            float2 o0, o1;
            o0.x = acc[mi][ni][0] + bb.x;
            o0.y = acc[mi][ni][1] + bb.y;
            o1.x = acc[mi][ni][2] + bb.x;
            o1.y = acc[mi][ni][3] + bb.y;
            *(float2*)(out + (size_t)m * DD + n) = o0;
            *(float2*)(out + (size_t)(m + 8) * DD + n) = o1;
        }
    }
}

// ---------------------------------------------------------------------------
extern "C" void kernel_launch(void* const* d_in, const int* in_sizes, int n_in,
                              void* d_out, int out_size) {
    const float* x = (const float*)d_in[0];   // [4,2048,4096] -> M=8192
    const float* W = (const float*)d_in[1];   // [4096,4096]
    const float* b = (const float*)d_in[2];   // [4096]
    float* out = (float*)d_out;

    cudaFuncSetAttribute(gemm_f16_kernel,
                         cudaFuncAttributeMaxDynamicSharedMemorySize, SMEM_TOTAL);

    prep_kernel<<<2 * DD, 512>>>(W, (const float4*)x);

    const int grid = (MM / TM) * (DD / TN);   // 64 * 32 = 2048
    gemm_f16_kernel<<<grid, NTHREADS, SMEM_TOTAL>>>(b, out);
}

// round 8
// speedup vs baseline: 2.8928x; 1.0050x over previous
#include <cuda_runtime.h>
#include <cuda_fp16.h>
#include <cstdint>
#include <cstddef>

#define DD 4096
#define MM 8192

// Scratch: Hadamard-rotated fp16 W [N,K]; fp16 x [M,K].
__device__ __align__(256) __half g_Wh[(size_t)DD * DD];
__device__ __align__(256) __half g_Xh[(size_t)MM * DD];

// ---------------------------------------------------------------------------
// Kernel 1 (fused prep):
//   blocks [0, 4096):     row-wise WHT of W (reg+shuffle+smem), /64, fp16
//   blocks [4096, 8192):  convert x to fp16
// (xH)W^T == x(WH)^T since H is symmetric.
// ---------------------------------------------------------------------------
__global__ void prep_kernel(const float* __restrict__ W,
                            const float4* __restrict__ x) {
    if (blockIdx.x < DD) {
        __shared__ float sh[DD];
        const int t = threadIdx.x;          // 512 threads
        const int lane = t & 31;
        const int w = t >> 5;
        const float4* src = (const float4*)(W + (size_t)blockIdx.x * DD) + t * 2;
        float v[8];
        {
            float4 u0 = src[0], u1 = src[1];
            v[0] = u0.x; v[1] = u0.y; v[2] = u0.z; v[3] = u0.w;
            v[4] = u1.x; v[5] = u1.y; v[6] = u1.z; v[7] = u1.w;
        }
#pragma unroll
        for (int len = 1; len <= 4; len <<= 1) {
#pragma unroll
            for (int e = 0; e < 8; ++e) {
                if ((e & len) == 0) {
                    float a = v[e], b = v[e | len];
                    v[e] = a + b;
                    v[e | len] = a - b;
                }
            }
        }
#pragma unroll
        for (int m = 1; m <= 16; m <<= 1) {
#pragma unroll
            for (int e = 0; e < 8; ++e) {
                float r = __shfl_xor_sync(0xffffffffu, v[e], m);
                v[e] = (lane & m) ? (r - v[e]) : (v[e] + r);
            }
        }
#pragma unroll
        for (int mw = 1; mw <= 8; mw <<= 1) {
            __syncthreads();
#pragma unroll
            for (int e = 0; e < 8; ++e) sh[t * 8 + e] = v[e];
            __syncthreads();
            const int p = (t ^ (mw * 32)) * 8;
#pragma unroll
            for (int e = 0; e < 8; ++e) {
                float r = sh[p + e];
                v[e] = (w & mw) ? (r - v[e]) : (v[e] + r);
            }
        }
        __half2 h[4];
#pragma unroll
        for (int e = 0; e < 4; ++e)
            h[e] = __floats2half2_rn(v[2 * e] * 0.015625f, v[2 * e + 1] * 0.015625f);
        uint4 o;
        o.x = *(uint32_t*)&h[0]; o.y = *(uint32_t*)&h[1];
        o.z = *(uint32_t*)&h[2]; o.w = *(uint32_t*)&h[3];
        *((uint4*)(g_Wh + (size_t)blockIdx.x * DD) + t) = o;
    } else {
        const size_t base = ((size_t)(blockIdx.x - DD) * blockDim.x + threadIdx.x) * 2;
#pragma unroll
        for (int u = 0; u < 2; ++u) {
            const size_t idx = base + u;
            float4 v0 = x[2 * idx];
            float4 v1 = x[2 * idx + 1];
            __half2 h0 = __floats2half2_rn(v0.x, v0.y);
            __half2 h1 = __floats2half2_rn(v0.z, v0.w);
            __half2 h2 = __floats2half2_rn(v1.x, v1.y);
            __half2 h3 = __floats2half2_rn(v1.z, v1.w);
            uint4 o;
            o.x = *(uint32_t*)&h0; o.y = *(uint32_t*)&h1;
            o.z = *(uint32_t*)&h2; o.w = *(uint32_t*)&h3;
            ((uint4*)g_Xh)[idx] = o;
        }
    }
}

// ---------------------------------------------------------------------------
// Kernel 2: fp16 mma.sync GEMM  out[M,N] = Xh[M,K] @ Wh[N,K]^T + bias
// CTA 128x128, 4 warps (2x2), warp tile 64x64, TKH=64 (128B rows),
// 3-stage cp.async, XOR-swizzled smem, TWO CTAs/SM, ~220 regs/thread:
// fragments explicitly double-buffered across k-steps to hide ldsm latency.
// ---------------------------------------------------------------------------
constexpr int TM = 128;
constexpr int TN = 128;
constexpr int TKH = 64;                      // halves per K-tile (128 B)
constexpr int NKT = DD / TKH;                // 64
constexpr int STAGES = 3;
constexpr int A_BYTES = TM * 128;            // 16384
constexpr int B_BYTES = TN * 128;            // 16384
constexpr int STAGE_BYTES = A_BYTES + B_BYTES;          // 32768
constexpr int SMEM_TOTAL = STAGES * STAGE_BYTES;        // 98304
constexpr int NTHREADS = 128;

__device__ __forceinline__ uint32_t smem_u32(const void* p) {
    return (uint32_t)__cvta_generic_to_shared(p);
}
__device__ __forceinline__ void cp16(uint32_t dst, const void* src) {
    asm volatile("cp.async.cg.shared.global [%0], [%1], 16;\n" :: "r"(dst), "l"(src));
}
__device__ __forceinline__ void ldsm4(uint32_t* r, uint32_t addr) {
    asm volatile("ldmatrix.sync.aligned.m8n8.x4.shared.b16 {%0,%1,%2,%3}, [%4];"
                 : "=r"(r[0]), "=r"(r[1]), "=r"(r[2]), "=r"(r[3]) : "r"(addr));
}
__device__ __forceinline__ void mma_f16(float* c, const uint32_t* a, const uint32_t* b) {
    asm volatile(
        "mma.sync.aligned.m16n8k16.row.col.f32.f16.f16.f32 "
        "{%0,%1,%2,%3}, {%4,%5,%6,%7}, {%8,%9}, {%0,%1,%2,%3};"
        : "+f"(c[0]), "+f"(c[1]), "+f"(c[2]), "+f"(c[3])
        : "r"(a[0]), "r"(a[1]), "r"(a[2]), "r"(a[3]),
          "r"(b[0]), "r"(b[1]));
}

// swizzled byte offset inside a 128B-wide tile
__device__ __forceinline__ uint32_t sw_off(int row, int chunk) {
    return (uint32_t)(row * 128 + ((chunk ^ (row & 7)) << 4));
}

__device__ __forceinline__ void issue_stage(int m0, int n0, int kt, int slot,
                                            uint32_t sbase, int tid) {
    const uint32_t stA = sbase + (uint32_t)(slot * STAGE_BYTES);
    const uint32_t stB = stA + A_BYTES;
    const __half* gA = g_Xh + (size_t)m0 * DD + kt * TKH;
    const __half* gB = g_Wh + (size_t)n0 * DD + kt * TKH;
#pragma unroll
    for (int i = 0; i < 8; ++i) {            // A: 1024 16B chunks
        const int idx = tid + i * NTHREADS;
        const int row = idx >> 3;
        const int c = idx & 7;
        cp16(stA + sw_off(row, c), gA + (size_t)row * DD + c * 8);
    }
#pragma unroll
    for (int i = 0; i < 8; ++i) {            // B: 1024 16B chunks
        const int idx = tid + i * NTHREADS;
        const int row = idx >> 3;
        const int c = idx & 7;
        cp16(stB + sw_off(row, c), gB + (size_t)row * DD + c * 8);
    }
    asm volatile("cp.async.commit_group;\n" ::: "memory");
}

__global__ void __launch_bounds__(NTHREADS, 2)
gemm_f16_kernel(const float* __restrict__ bias, float* __restrict__ out) {
    extern __shared__ char smem[];
    const uint32_t sbase = smem_u32(smem);
    const int tid = threadIdx.x;
    const int wid = tid >> 5;
    const int lane = tid & 31;
    const int g = lane >> 2;              // accumulator row within 8
    const int nc2 = (lane & 3) * 2;       // accumulator n-col base
    const int wm = wid & 1;               // 2 warps along M (64 rows each)
    const int wn = wid >> 1;              // 2 warps along N (64 cols each)

    // per-lane ldmatrix row/chunk components
    const int a_row = lane & 15;
    const int a_cofs = lane >> 4;                       // 0/1
    const int b_row = ((lane >> 4) << 3) + (lane & 7);
    const int b_cofs = (lane >> 3) & 1;                 // 0/1

    // CTA swizzle: groups of 16 M-tiles sweep all 32 N-tiles (L2 locality)
    constexpr int PN = DD / TN;           // 32
    constexpr int G = 16;
    const int pid = blockIdx.x;
    const int grp = pid / (G * PN);
    const int pm = grp * G + (pid % G);
    const int pn = (pid % (G * PN)) / G;
    const int m0 = pm * TM;
    const int n0 = pn * TN;

    float acc[4][8][4];
#pragma unroll
    for (int mi = 0; mi < 4; ++mi)
#pragma unroll
        for (int ni = 0; ni < 8; ++ni)
#pragma unroll
            for (int v = 0; v < 4; ++v) acc[mi][ni][v] = 0.0f;

#pragma unroll
    for (int kt = 0; kt < STAGES - 1; ++kt)
        issue_stage(m0, n0, kt, kt, sbase, tid);

    for (int kt = 0; kt < NKT; ++kt) {
        const int rem = NKT - 1 - kt;
        if (rem >= STAGES - 2) {
            asm volatile("cp.async.wait_group %0;\n" :: "n"(STAGES - 2) : "memory");
        } else {
            asm volatile("cp.async.wait_group 0;\n" ::: "memory");
        }
        __syncthreads();

        const int nk = kt + STAGES - 1;
        if (nk < NKT)
            issue_stage(m0, n0, nk, nk % STAGES, sbase, tid);

        const uint32_t sA = sbase + (uint32_t)((kt % STAGES) * STAGE_BYTES);
        const uint32_t sB = sA + A_BYTES;

        // double-buffered fragments: load step s+1 while computing step s
        uint32_t a[2][4][4];
        uint32_t bf[2][4][4];
#pragma unroll
        for (int mi = 0; mi < 4; ++mi)
            ldsm4(a[0][mi], sA + sw_off(wm * 64 + mi * 16 + a_row, a_cofs));
#pragma unroll
        for (int j = 0; j < 4; ++j)
            ldsm4(bf[0][j], sB + sw_off(wn * 64 + j * 16 + b_row, b_cofs));

#pragma unroll
        for (int s = 0; s < TKH / 16; ++s) {   // 4 k16 steps
            const int cur = s & 1;
            const int nxt = cur ^ 1;
            if (s < TKH / 16 - 1) {
#pragma unroll
                for (int mi = 0; mi < 4; ++mi)
                    ldsm4(a[nxt][mi],
                          sA + sw_off(wm * 64 + mi * 16 + a_row, 2 * (s + 1) + a_cofs));
#pragma unroll
                for (int j = 0; j < 4; ++j)
                    ldsm4(bf[nxt][j],
                          sB + sw_off(wn * 64 + j * 16 + b_row, 2 * (s + 1) + b_cofs));
            }
#pragma unroll
            for (int mi = 0; mi < 4; ++mi)
#pragma unroll
                for (int ni = 0; ni < 8; ++ni)
                    mma_f16(acc[mi][ni], a[cur][mi], &bf[cur][ni >> 1][(ni & 1) * 2]);
        }
    }

    // epilogue
#pragma unroll
    for (int mi = 0; mi < 4; ++mi) {
        const int m = m0 + wm * 64 + mi * 16 + g;
#pragma unroll
        for (int ni = 0; ni < 8; ++ni) {
            const int n = n0 + wn * 64 + ni * 8 + nc2;
            const float2 bb = *(const float2*)(bias + n);
            float2 o0, o1;
            o0.x = acc[mi][ni][0] + bb.x;
            o0.y = acc[mi][ni][1] + bb.y;
            o1.x = acc[mi][ni][2] + bb.x;
            o1.y = acc[mi][ni][3] + bb.y;
            *(float2*)(out + (size_t)m * DD + n) = o0;
            *(float2*)(out + (size_t)(m + 8) * DD + n) = o1;
        }
    }
}

// ---------------------------------------------------------------------------
extern "C" void kernel_launch(void* const* d_in, const int* in_sizes, int n_in,
                              void* d_out, int out_size) {
    const float* x = (const float*)d_in[0];   // [4,2048,4096] -> M=8192
    const float* W = (const float*)d_in[1];   // [4096,4096]
    const float* b = (const float*)d_in[2];   // [4096]
    float* out = (float*)d_out;

    cudaFuncSetAttribute(gemm_f16_kernel,
                         cudaFuncAttributeMaxDynamicSharedMemorySize, SMEM_TOTAL);

    prep_kernel<<<2 * DD, 512>>>(W, (const float4*)x);

    const int grid = (MM / TM) * (DD / TN);   // 64 * 32 = 2048
    gemm_f16_kernel<<<grid, NTHREADS, SMEM_TOTAL>>>(b, out);
}